// round 1
// baseline (speedup 1.0000x reference)
#include <cuda_runtime.h>
#include <cstdint>

// Problem constants (fixed shapes for this problem)
#define MB 8192      // B*S
#define HH 1024      // H
#define RR 2048      // R (= L)
#define LL 2048
#define SS 2048
#define BB 4

// 6 scratch slabs of [MB, RR] fp32: f, g, c, q, up, gate  (402 MB total)
__device__ float g_scratch[6ull * MB * RR];

// ---------------------------------------------------------------------------
// SGEMM: C[M,N] = act( A[M,K] @ W[N,K]^T )   (optionally += existing C)
// A row-major [M,K], W row-major [N,K] (torch Linear weight layout).
// Block tile 128x128, K-tile 8, 8x8 per thread, 256 threads,
// register-prefetch pipelining of global loads.
// ---------------------------------------------------------------------------
#define BM 128
#define BN 128
#define BK 8
#define TM 8
#define TN 8

__device__ __forceinline__ float act_apply(float x, int act) {
    if (act == 1) return tanhf(x);                         // tanh
    if (act == 2) return 1.0f / (1.0f + __expf(-x));       // sigmoid
    if (act == 3) return x / (1.0f + __expf(-x));          // silu
    return x;
}

__global__ __launch_bounds__(256, 2)
void sgemm_tn(const float* __restrict__ A, const float* __restrict__ W,
              float* C, int M, int N, int K, int act, int accum)
{
    __shared__ float As[BK][BM];
    __shared__ float Bs[BK][BN];

    const int tid = threadIdx.x;
    const int tx  = tid & 15;          // 0..15  (n direction)
    const int ty  = tid >> 4;          // 0..15  (m direction)
    const int bm  = blockIdx.y * BM;
    const int bnn = blockIdx.x * BN;

    // Global-load mapping: 256 threads cover 128 rows x 2 float4 per tile
    const int lrow = tid >> 1;            // 0..127
    const int lk4  = (tid & 1) << 2;      // 0 or 4

    const float* Ag = A + (size_t)(bm  + lrow) * K + lk4;
    const float* Wg = W + (size_t)(bnn + lrow) * K + lk4;

    float4 a_n = *(const float4*)Ag;
    float4 b_n = *(const float4*)Wg;

    float acc[TM][TN];
#pragma unroll
    for (int i = 0; i < TM; ++i)
#pragma unroll
        for (int j = 0; j < TN; ++j) acc[i][j] = 0.0f;

    const int nk = K / BK;
    for (int kt = 0; kt < nk; ++kt) {
        // stage -> smem (transposed: [k][m] / [k][n])
        As[lk4 + 0][lrow] = a_n.x;  As[lk4 + 1][lrow] = a_n.y;
        As[lk4 + 2][lrow] = a_n.z;  As[lk4 + 3][lrow] = a_n.w;
        Bs[lk4 + 0][lrow] = b_n.x;  Bs[lk4 + 1][lrow] = b_n.y;
        Bs[lk4 + 2][lrow] = b_n.z;  Bs[lk4 + 3][lrow] = b_n.w;
        __syncthreads();

        // prefetch next k-tile while computing this one
        if (kt + 1 < nk) {
            a_n = *(const float4*)(Ag + (size_t)(kt + 1) * BK);
            b_n = *(const float4*)(Wg + (size_t)(kt + 1) * BK);
        }

#pragma unroll
        for (int k = 0; k < BK; ++k) {
            float4 a0 = *(const float4*)&As[k][ty * TM];
            float4 a1 = *(const float4*)&As[k][ty * TM + 4];
            float4 b0 = *(const float4*)&Bs[k][tx * TN];
            float4 b1 = *(const float4*)&Bs[k][tx * TN + 4];
            float ra[TM] = {a0.x, a0.y, a0.z, a0.w, a1.x, a1.y, a1.z, a1.w};
            float rb[TN] = {b0.x, b0.y, b0.z, b0.w, b1.x, b1.y, b1.z, b1.w};
#pragma unroll
            for (int i = 0; i < TM; ++i)
#pragma unroll
                for (int j = 0; j < TN; ++j)
                    acc[i][j] = fmaf(ra[i], rb[j], acc[i][j]);
        }
        __syncthreads();
    }

    // epilogue
#pragma unroll
    for (int i = 0; i < TM; ++i) {
        const size_t m = (size_t)(bm + ty * TM + i);
#pragma unroll
        for (int j = 0; j < TN; j += 4) {
            const size_t n = (size_t)(bnn + tx * TN + j);
            float4 v;
            v.x = act_apply(acc[i][j + 0], act);
            v.y = act_apply(acc[i][j + 1], act);
            v.z = act_apply(acc[i][j + 2], act);
            v.w = act_apply(acc[i][j + 3], act);
            if (accum) {
                float4 c0 = *(const float4*)&C[m * N + n];
                v.x += c0.x; v.y += c0.y; v.z += c0.z; v.w += c0.w;
            }
            *(float4*)&C[m * N + n] = v;
        }
    }
}

// ---------------------------------------------------------------------------
// Diagonal linear recurrence + fused readout:
//   state_s = f_s * state_{s-1} + g_s * c_s     (state_{-1} = s0[r])
//   RO[b,s,r] = silu(q[b,s,r] * state_s)
// One thread per (b, r) channel; loads coalesced across r.
// ---------------------------------------------------------------------------
__global__ void recur_kernel(const float* __restrict__ F, const float* __restrict__ G,
                             const float* __restrict__ Cc, const float* __restrict__ Q,
                             const float* __restrict__ s0, float* RO)
{
    const int t = blockIdx.x * blockDim.x + threadIdx.x;   // 0 .. BB*RR-1
    const int b = t / RR;
    const int r = t - b * RR;
    const size_t base = (size_t)b * SS * RR + r;

    float state = s0[r];
#pragma unroll 4
    for (int s = 0; s < SS; ++s) {
        const size_t idx = base + (size_t)s * RR;
        const float f  = F[idx];
        const float gc = G[idx] * Cc[idx];
        state = fmaf(f, state, gc);
        const float x = Q[idx] * state;
        RO[idx] = x / (1.0f + __expf(-x));   // silu
    }
}

// hp = up * gate (elementwise, in-place into up), float4 vectorized
__global__ void mul_kernel(float* __restrict__ up, const float* __restrict__ gate, int n4)
{
    const int i = blockIdx.x * blockDim.x + threadIdx.x;
    if (i < n4) {
        float4 u = ((float4*)up)[i];
        const float4 g = ((const float4*)gate)[i];
        u.x *= g.x; u.y *= g.y; u.z *= g.z; u.w *= g.w;
        ((float4*)up)[i] = u;
    }
}

// ---------------------------------------------------------------------------
extern "C" void kernel_launch(void* const* d_in, const int* in_sizes, int n_in,
                              void* d_out, int out_size)
{
    const float* x   = (const float*)d_in[0];   // [B,S,H]
    const float* Wf  = (const float*)d_in[1];   // [R,H]
    const float* Wi  = (const float*)d_in[2];   // [R,H]
    const float* Wv  = (const float*)d_in[3];   // [R,H]
    const float* Wq  = (const float*)d_in[4];   // [R,H]
    const float* Wro = (const float*)d_in[5];   // [H,R]
    const float* Wu  = (const float*)d_in[6];   // [L,H]
    const float* Wg  = (const float*)d_in[7];   // [L,H]
    const float* Wd  = (const float*)d_in[8];   // [H,L]
    const float* s0  = (const float*)d_in[9];   // [R]
    float* out = (float*)d_out;                 // [B,S,H]

    float* scr = nullptr;
    cudaGetSymbolAddress((void**)&scr, g_scratch);
    float* f  = scr + 0ull * MB * RR;
    float* g  = scr + 1ull * MB * RR;
    float* c  = scr + 2ull * MB * RR;
    float* q  = scr + 3ull * MB * RR;   // readout written in-place here
    float* up = scr + 4ull * MB * RR;   // hp written in-place here
    float* gt = scr + 5ull * MB * RR;

    const dim3 blk(256);
    const dim3 gproj(RR / BN, MB / BM);   // (16, 64)

    // Projections with fused activations
    sgemm_tn<<<gproj, blk>>>(x, Wf, f,  MB, RR, HH, /*tanh*/1, 0);
    sgemm_tn<<<gproj, blk>>>(x, Wi, g,  MB, RR, HH, /*sigm*/2, 0);
    sgemm_tn<<<gproj, blk>>>(x, Wv, c,  MB, RR, HH, /*silu*/3, 0);
    sgemm_tn<<<gproj, blk>>>(x, Wq, q,  MB, RR, HH, /*none*/0, 0);
    sgemm_tn<<<gproj, blk>>>(x, Wu, up, MB, RR, HH, /*none*/0, 0);
    sgemm_tn<<<gproj, blk>>>(x, Wg, gt, MB, RR, HH, /*silu*/3, 0);

    // Scan + fused readout (writes silu(q*state) over q's buffer)
    recur_kernel<<<(BB * RR) / 256, 256>>>(f, g, c, q, s0, q);

    // hp = up * silu-gated gate
    mul_kernel<<<(MB * LL / 4) / 256, 256>>>(up, gt, MB * LL / 4);

    // out = readout @ Wro^T ; out += hp @ Wd^T
    const dim3 gout(HH / BN, MB / BM);    // (8, 64)
    sgemm_tn<<<gout, blk>>>(q,  Wro, out, MB, HH, RR, 0, /*accum*/0);
    sgemm_tn<<<gout, blk>>>(up, Wd,  out, MB, HH, LL, 0, /*accum*/1);
}

// round 2
// speedup vs baseline: 3.0628x; 3.0628x over previous
#include <cuda_runtime.h>
#include <cstdint>

// Problem constants
#define MB 8192      // B*S
#define HH 1024      // H
#define RR 2048      // R (= L)
#define SS 2048
#define BB 4
#define NCH 32       // scan chunks
#define CH  64       // steps per chunk (SS/NCH)

// scratch: 6 slabs [MB,RR] + 3 chunk arrays [BB,NCH,RR]
__device__ float g_scratch[6ull * MB * RR + 3ull * BB * NCH * RR];

// ---------------------------------------------------------------------------
// TF32 tensor-core GEMM: C[M,N] = act( A[M,K] @ W[N,K]^T )
// CTA tile 128x128, BK=16, 8 warps (warp tile 64x32), mma.sync m16n8k8.tf32.
// smem [row][16] fp32 with float4-block XOR swizzle: block' = blk ^ ((row>>1)&3)
// ---------------------------------------------------------------------------
#define BM 128
#define BN 128
#define BK 16

__device__ __forceinline__ float to_tf32(float x) {
    unsigned u;
    asm("cvt.rna.tf32.f32 %0, %1;" : "=r"(u) : "f"(x));
    return __uint_as_float(u);
}

__device__ __forceinline__ void mma_tf32(float c[4], const float a[4], const float b[2]) {
    asm volatile(
        "mma.sync.aligned.m16n8k8.row.col.f32.tf32.tf32.f32 "
        "{%0,%1,%2,%3}, {%4,%5,%6,%7}, {%8,%9}, {%0,%1,%2,%3};"
        : "+f"(c[0]), "+f"(c[1]), "+f"(c[2]), "+f"(c[3])
        : "r"(__float_as_uint(a[0])), "r"(__float_as_uint(a[1])),
          "r"(__float_as_uint(a[2])), "r"(__float_as_uint(a[3])),
          "r"(__float_as_uint(b[0])), "r"(__float_as_uint(b[1])));
}

// swizzled float index into a [rows][16] tile
__device__ __forceinline__ int swz16(int row, int col) {
    int blk = (col >> 2) ^ ((row >> 1) & 3);
    return row * 16 + (blk << 2) + (col & 3);
}

__device__ __forceinline__ float act_apply(float x, int act) {
    if (act == 1) return tanhf(x);
    if (act == 2) return 1.0f / (1.0f + __expf(-x));
    if (act == 3) return x / (1.0f + __expf(-x));
    return x;
}

// Core K-loop: accumulates A[bm:bm+128, :K] @ W[bn:bn+128, :K]^T into acc.
__device__ __forceinline__ void gemm_core(
    const float* __restrict__ A, const float* __restrict__ W, int K,
    int bm, int bn, int tid,
    float* As, float* Bs,          // each 2 * 128*16 floats (double buffered)
    float acc[4][4][4])
{
    const int lane = tid & 31;
    const int wid  = tid >> 5;
    const int wm   = (wid >> 2) * 64;   // 0 or 64
    const int wn   = (wid & 3) * 32;    // 0,32,64,96
    const int fr   = lane >> 2;         // 0..7
    const int fc   = lane & 3;          // 0..3

    // loader mapping: 2 float4 per thread
    const int lr = tid >> 2;            // 0..63 (+64 for i=1)
    const int lc4 = tid & 3;            // float4 block 0..3

    const int nk = K / BK;

    // load tile 0
    float4 va[2], vb[2];
#pragma unroll
    for (int i = 0; i < 2; ++i) {
        const int row = lr + i * 64;
        va[i] = *(const float4*)(A + (size_t)(bm + row) * K + lc4 * 4);
        vb[i] = *(const float4*)(W + (size_t)(bn + row) * K + lc4 * 4);
    }
#pragma unroll
    for (int i = 0; i < 2; ++i) {
        const int row = lr + i * 64;
        const int pb = lc4 ^ ((row >> 1) & 3);
        float4 wa, wb;
        wa.x = to_tf32(va[i].x); wa.y = to_tf32(va[i].y); wa.z = to_tf32(va[i].z); wa.w = to_tf32(va[i].w);
        wb.x = to_tf32(vb[i].x); wb.y = to_tf32(vb[i].y); wb.z = to_tf32(vb[i].z); wb.w = to_tf32(vb[i].w);
        *(float4*)(As + row * 16 + pb * 4) = wa;
        *(float4*)(Bs + row * 16 + pb * 4) = wb;
    }
    __syncthreads();

    for (int kt = 0; kt < nk; ++kt) {
        float* curA = As + (kt & 1) * 2048;
        float* curB = Bs + (kt & 1) * 2048;
        float* nxtA = As + ((kt + 1) & 1) * 2048;
        float* nxtB = Bs + ((kt + 1) & 1) * 2048;

        // prefetch next tile
        if (kt + 1 < nk) {
            const int k0 = (kt + 1) * BK;
#pragma unroll
            for (int i = 0; i < 2; ++i) {
                const int row = lr + i * 64;
                va[i] = *(const float4*)(A + (size_t)(bm + row) * K + k0 + lc4 * 4);
                vb[i] = *(const float4*)(W + (size_t)(bn + row) * K + k0 + lc4 * 4);
            }
        }

        // compute: 2 k-steps of 8
#pragma unroll
        for (int g = 0; g < 2; ++g) {
            const int kb = g * 8;
            float af[4][4];
#pragma unroll
            for (int ms = 0; ms < 4; ++ms) {
                const int r0 = wm + ms * 16 + fr;
                af[ms][0] = curA[swz16(r0,     kb + fc)];
                af[ms][1] = curA[swz16(r0 + 8, kb + fc)];
                af[ms][2] = curA[swz16(r0,     kb + fc + 4)];
                af[ms][3] = curA[swz16(r0 + 8, kb + fc + 4)];
            }
            float bf[4][2];
#pragma unroll
            for (int ns = 0; ns < 4; ++ns) {
                const int n0 = wn + ns * 8 + fr;
                bf[ns][0] = curB[swz16(n0, kb + fc)];
                bf[ns][1] = curB[swz16(n0, kb + fc + 4)];
            }
#pragma unroll
            for (int ms = 0; ms < 4; ++ms)
#pragma unroll
                for (int ns = 0; ns < 4; ++ns)
                    mma_tf32(acc[ms][ns], af[ms], bf[ns]);
        }

        // store prefetched tile
        if (kt + 1 < nk) {
#pragma unroll
            for (int i = 0; i < 2; ++i) {
                const int row = lr + i * 64;
                const int pb = lc4 ^ ((row >> 1) & 3);
                float4 wa, wb;
                wa.x = to_tf32(va[i].x); wa.y = to_tf32(va[i].y); wa.z = to_tf32(va[i].z); wa.w = to_tf32(va[i].w);
                wb.x = to_tf32(vb[i].x); wb.y = to_tf32(vb[i].y); wb.z = to_tf32(vb[i].z); wb.w = to_tf32(vb[i].w);
                *(float4*)(nxtA + row * 16 + pb * 4) = wa;
                *(float4*)(nxtB + row * 16 + pb * 4) = wb;
            }
        }
        __syncthreads();
    }
}

__device__ __forceinline__ void epilogue(
    float* __restrict__ O, int ldn, int bm, int bn, int tid,
    float acc[4][4][4], int act)
{
    const int lane = tid & 31;
    const int wid  = tid >> 5;
    const int wm   = (wid >> 2) * 64;
    const int wn   = (wid & 3) * 32;
    const int fr   = lane >> 2;
    const int fc   = lane & 3;

#pragma unroll
    for (int ms = 0; ms < 4; ++ms) {
#pragma unroll
        for (int ns = 0; ns < 4; ++ns) {
            const int m0 = bm + wm + ms * 16 + fr;
            const int n0 = bn + wn + ns * 8 + 2 * fc;
            float2 v0, v1;
            v0.x = act_apply(acc[ms][ns][0], act);
            v0.y = act_apply(acc[ms][ns][1], act);
            v1.x = act_apply(acc[ms][ns][2], act);
            v1.y = act_apply(acc[ms][ns][3], act);
            *(float2*)&O[(size_t)m0 * ldn + n0] = v0;
            *(float2*)&O[(size_t)(m0 + 8) * ldn + n0] = v1;
        }
    }
}

// Fused 6-projection kernel: grid (N/128=16, 6 weights, M/128=64)
__global__ __launch_bounds__(256, 2)
void proj_kernel(const float* __restrict__ x,
                 const float* __restrict__ W0, const float* __restrict__ W1,
                 const float* __restrict__ W2, const float* __restrict__ W3,
                 const float* __restrict__ W4, const float* __restrict__ W5,
                 float* o0, float* o1, float* o2, float* o3, float* o4, float* o5)
{
    __shared__ float As[2 * 2048];
    __shared__ float Bs[2 * 2048];

    const int tid = threadIdx.x;
    const int bm = blockIdx.z * BM;
    const int bn = blockIdx.x * BN;

    const float* W; float* O; int act;
    switch (blockIdx.y) {
        case 0:  W = W0; O = o0; act = 1; break;  // forget: tanh
        case 1:  W = W1; O = o1; act = 2; break;  // input: sigmoid
        case 2:  W = W2; O = o2; act = 3; break;  // value: silu
        case 3:  W = W3; O = o3; act = 0; break;  // query
        case 4:  W = W4; O = o4; act = 0; break;  // up
        default: W = W5; O = o5; act = 3; break;  // gate: silu
    }

    float acc[4][4][4];
#pragma unroll
    for (int i = 0; i < 4; ++i)
#pragma unroll
        for (int j = 0; j < 4; ++j)
#pragma unroll
            for (int k = 0; k < 4; ++k) acc[i][j][k] = 0.0f;

    gemm_core(x, W, HH, bm, bn, tid, As, Bs, acc);
    epilogue(O, RR, bm, bn, tid, acc, act);
}

// Fused output kernel: out = RO @ Wro^T + HP @ Wd^T   (both K=2048)
__global__ __launch_bounds__(256, 2)
void out_kernel(const float* __restrict__ A1, const float* __restrict__ W1,
                const float* __restrict__ A2, const float* __restrict__ W2,
                float* __restrict__ O)
{
    __shared__ float As[2 * 2048];
    __shared__ float Bs[2 * 2048];

    const int tid = threadIdx.x;
    const int bm = blockIdx.z * BM;
    const int bn = blockIdx.x * BN;

    float acc[4][4][4];
#pragma unroll
    for (int i = 0; i < 4; ++i)
#pragma unroll
        for (int j = 0; j < 4; ++j)
#pragma unroll
            for (int k = 0; k < 4; ++k) acc[i][j][k] = 0.0f;

    gemm_core(A1, W1, RR, bm, bn, tid, As, Bs, acc);
    __syncthreads();
    gemm_core(A2, W2, RR, bm, bn, tid, As, Bs, acc);
    epilogue(O, HH, bm, bn, tid, acc, 0);
}

// ---------------------------------------------------------------------------
// Chunked parallel scan (3 phases)
// ---------------------------------------------------------------------------
__global__ void scan_p1(const float* __restrict__ F, const float* __restrict__ G,
                        const float* __restrict__ C,
                        float* __restrict__ chA, float* __restrict__ chY)
{
    const int t  = blockIdx.x * blockDim.x + threadIdx.x;   // BB*NCH*RR threads
    const int r  = t & (RR - 1);
    const int bc = t >> 11;
    const int ch = bc & (NCH - 1);
    const int b  = bc >> 5;

    const size_t base = ((size_t)b * SS + (size_t)ch * CH) * RR + r;
    float a = 1.0f, y = 0.0f;
#pragma unroll 4
    for (int s = 0; s < CH; ++s) {
        const size_t idx = base + (size_t)s * RR;
        const float f  = F[idx];
        const float gc = G[idx] * C[idx];
        y = fmaf(f, y, gc);
        a *= f;
    }
    const int o = (b * NCH + ch) * RR + r;
    chA[o] = a;
    chY[o] = y;
}

__global__ void scan_p2(const float* __restrict__ chA, const float* __restrict__ chY,
                        const float* __restrict__ s0, float* __restrict__ carry)
{
    const int t = blockIdx.x * blockDim.x + threadIdx.x;    // BB*RR threads
    const int r = t & (RR - 1);
    const int b = t >> 11;

    float c = s0[r];
#pragma unroll
    for (int ch = 0; ch < NCH; ++ch) {
        const int o = (b * NCH + ch) * RR + r;
        carry[o] = c;
        c = fmaf(chA[o], c, chY[o]);
    }
}

__global__ void scan_p3(const float* __restrict__ F, const float* __restrict__ G,
                        const float* __restrict__ C, const float* __restrict__ Q,
                        const float* __restrict__ carry, float* __restrict__ RO)
{
    const int t  = blockIdx.x * blockDim.x + threadIdx.x;
    const int r  = t & (RR - 1);
    const int bc = t >> 11;
    const int ch = bc & (NCH - 1);
    const int b  = bc >> 5;

    const size_t base = ((size_t)b * SS + (size_t)ch * CH) * RR + r;
    float state = carry[(b * NCH + ch) * RR + r];
#pragma unroll 4
    for (int s = 0; s < CH; ++s) {
        const size_t idx = base + (size_t)s * RR;
        const float f  = F[idx];
        const float gc = G[idx] * C[idx];
        state = fmaf(f, state, gc);
        const float xq = Q[idx] * state;
        RO[idx] = xq / (1.0f + __expf(-xq));
    }
}

__global__ void mul_kernel(float* __restrict__ up, const float* __restrict__ gate, int n4)
{
    const int i = blockIdx.x * blockDim.x + threadIdx.x;
    if (i < n4) {
        float4 u = ((float4*)up)[i];
        const float4 g = ((const float4*)gate)[i];
        u.x *= g.x; u.y *= g.y; u.z *= g.z; u.w *= g.w;
        ((float4*)up)[i] = u;
    }
}

// ---------------------------------------------------------------------------
extern "C" void kernel_launch(void* const* d_in, const int* in_sizes, int n_in,
                              void* d_out, int out_size)
{
    const float* x   = (const float*)d_in[0];
    const float* Wf  = (const float*)d_in[1];
    const float* Wi  = (const float*)d_in[2];
    const float* Wv  = (const float*)d_in[3];
    const float* Wq  = (const float*)d_in[4];
    const float* Wro = (const float*)d_in[5];
    const float* Wu  = (const float*)d_in[6];
    const float* Wg  = (const float*)d_in[7];
    const float* Wd  = (const float*)d_in[8];
    const float* s0  = (const float*)d_in[9];
    float* out = (float*)d_out;

    float* scr = nullptr;
    cudaGetSymbolAddress((void**)&scr, g_scratch);
    float* f   = scr + 0ull * MB * RR;
    float* g   = scr + 1ull * MB * RR;
    float* c   = scr + 2ull * MB * RR;
    float* q   = scr + 3ull * MB * RR;   // readout written in-place
    float* up  = scr + 4ull * MB * RR;   // hp written in-place
    float* gt  = scr + 5ull * MB * RR;
    float* chA = scr + 6ull * MB * RR;
    float* chY = chA + (size_t)BB * NCH * RR;
    float* car = chY + (size_t)BB * NCH * RR;

    // 1. all six projections, one launch (A panel reused across y)
    dim3 gproj(RR / BN, 6, MB / BM);     // (16, 6, 64)
    proj_kernel<<<gproj, 256>>>(x, Wf, Wi, Wv, Wq, Wu, Wg, f, g, c, q, up, gt);

    // 2. chunked scan + fused readout
    scan_p1<<<(BB * NCH * RR) / 256, 256>>>(f, g, c, chA, chY);
    scan_p2<<<(BB * RR) / 256, 256>>>(chA, chY, s0, car);
    scan_p3<<<(BB * NCH * RR) / 256, 256>>>(f, g, c, q, car, q);

    // 3. hp = up * silu(gate)  (gate already silu'd in projection)
    mul_kernel<<<(MB * RR / 4) / 256, 256>>>(up, gt, MB * RR / 4);

    // 4. out = RO @ Wro^T + HP @ Wd^T (single fused kernel)
    dim3 gout(HH / BN, 1, MB / BM);      // (8, 1, 64)
    out_kernel<<<gout, 256>>>(q, Wro, up, Wd, out);
}